// round 2
// baseline (speedup 1.0000x reference)
#include <cuda_runtime.h>

#define N_NODES 100000
#define N_EDGES 1600000
#define NRELS 8
#define HID 128
#define N_TYPES 250
#define NG 64
#define NCLS 49
#define PROJ_COLS 1152   // 8*128 rel columns + 128 root columns

// ---- scratch (device globals; no allocation allowed) ----
__device__ __align__(16) float g_proj[N_TYPES * PROJ_COLS];   // 1.15 MB, L2-resident
__device__ float g_cnt[N_NODES * NRELS];                      // 3.2 MB
__device__ __align__(16) float g_agg[(size_t)N_NODES * HID];  // 51.2 MB
__device__ float g_seg[NG * HID];
__device__ float g_segcnt[NG];

// Zero the accumulators that get atomically updated each replay.
__global__ void k_zero() {
    int i = blockIdx.x * blockDim.x + threadIdx.x;
    if (i < N_NODES * NRELS) g_cnt[i] = 0.f;
    if (i < NG * HID) g_seg[i] = 0.f;
    if (i < NG) g_segcnt[i] = 0.f;
}

// proj[t][c] = sum_d emb[t][d] * Wcat[d][c]
//   c in [0,1024): r = c>>7, h = c&127  -> w_rel[r][d][h]
//   c in [1024,1152): h = c-1024        -> w_root[d][h]
__global__ void k_proj(const float* __restrict__ emb,
                       const float* __restrict__ w_rel,
                       const float* __restrict__ w_root) {
    __shared__ float semb[10][128];
    int bx = blockIdx.x;
    int y0 = blockIdx.y * 10;
    int tid = threadIdx.x;
    for (int idx = tid; idx < 10 * 128; idx += 128) {
        int row = idx >> 7, d = idx & 127;
        semb[row][d] = emb[(y0 + row) * 128 + d];
    }
    __syncthreads();
    float acc[10];
#pragma unroll
    for (int t = 0; t < 10; t++) acc[t] = 0.f;
    const float* wp = (bx < 8) ? (w_rel + (size_t)bx * 128 * 128 + tid)
                               : (w_root + tid);
#pragma unroll 4
    for (int d = 0; d < 128; d++) {
        float wv = wp[(size_t)d * 128];
#pragma unroll
        for (int t = 0; t < 10; t++) acc[t] += semb[t][d] * wv;
    }
    int c = bx * 128 + tid;
#pragma unroll
    for (int t = 0; t < 10; t++) g_proj[(y0 + t) * PROJ_COLS + c] = acc[t];
}

// cnt[dst][r] += 1 per edge
__global__ void k_cnt(const int* __restrict__ ei,
                      const int* __restrict__ et) {
    int e = blockIdx.x * blockDim.x + threadIdx.x;
    if (e >= N_EDGES) return;
    int dst = ei[N_EDGES + e];
    int r = et[e];
    atomicAdd(&g_cnt[dst * NRELS + r], 1.0f);
}

// agg[n] = proj[x[n]][1024:1152] + bias    (root term + bias, pre-scatter)
__global__ void k_init(const int* __restrict__ x,
                       const float* __restrict__ bias) {
    int i = blockIdx.x * blockDim.x + threadIdx.x;  // n*32 + j (float4 lanes)
    if (i >= N_NODES * 32) return;
    int n = i >> 5, j = i & 31;
    int t = x[n];
    const float4* p = (const float4*)g_proj;
    float4 v = p[t * (PROJ_COLS / 4) + 256 + j];
    const float4* b4 = (const float4*)bias;
    float4 b = b4[j];
    v.x += b.x; v.y += b.y; v.z += b.z; v.w += b.w;
    float4* a = (float4*)g_agg;
    a[(size_t)n * 32 + j] = v;
}

// Per edge: agg[dst] += proj[x[src]][r*128 : r*128+128] / max(cnt[dst,r],1)
// One warp per edge, one float4 per lane, red.global.add.v4.f32 scatter.
__global__ void k_edge(const int* __restrict__ ei,
                       const int* __restrict__ et,
                       const int* __restrict__ x) {
    int gt = blockIdx.x * blockDim.x + threadIdx.x;
    int e = gt >> 5;
    int lane = gt & 31;
    if (e >= N_EDGES) return;
    int src = ei[e];
    int dst = ei[N_EDGES + e];
    int r = et[e];
    int t = x[src];
    float c = g_cnt[dst * NRELS + r];
    float w = 1.0f / fmaxf(c, 1.0f);
    const float4* p = (const float4*)g_proj;
    float4 v = p[t * (PROJ_COLS / 4) + r * 32 + lane];
    float4* a = (float4*)g_agg + (size_t)dst * 32 + lane;
    asm volatile("red.global.add.v4.f32 [%0], {%1,%2,%3,%4};"
                 :: "l"(a), "f"(v.x * w), "f"(v.y * w), "f"(v.z * w), "f"(v.w * w)
                 : "memory");
}

// h = relu(agg); masked segment sums over sorted batch.
__global__ void k_seg(const int* __restrict__ batch,
                      const int* __restrict__ ntype) {
    int tid = threadIdx.x;
    int n0 = blockIdx.x * 128;
    int nend = min(n0 + 128, N_NODES);
    int gprev = batch[n0];
    float acc = 0.f, cacc = 0.f;
    for (int n = n0; n < nend; n++) {
        int g = batch[n];
        if (g != gprev) {
            atomicAdd(&g_seg[gprev * HID + tid], acc);
            if (tid == 0) atomicAdd(&g_segcnt[gprev], cacc);
            acc = 0.f; cacc = 0.f; gprev = g;
        }
        float h = fmaxf(g_agg[(size_t)n * HID + tid], 0.f);
        if (ntype[n] == 0) { acc += h; cacc += 1.f; }
    }
    atomicAdd(&g_seg[gprev * HID + tid], acc);
    if (tid == 0) atomicAdd(&g_segcnt[gprev], cacc);
}

// out[g][o] = (seg[g]/max(cnt,1)) . lin_w[o] + lin_b[o]
__global__ void k_out(const float* __restrict__ lw,
                      const float* __restrict__ lb,
                      float* __restrict__ out) {
    __shared__ float s[128];
    int g = blockIdx.x, tid = threadIdx.x;
    float c = g_segcnt[g];
    float inv = 1.0f / fmaxf(c, 1.0f);
    s[tid] = g_seg[g * HID + tid] * inv;
    __syncthreads();
    if (tid < NCLS) {
        float acc = lb[tid];
#pragma unroll 4
        for (int d = 0; d < 128; d++) acc += s[d] * lw[tid * 128 + d];
        out[g * NCLS + tid] = acc;
    }
}

extern "C" void kernel_launch(void* const* d_in, const int* in_sizes, int n_in,
                              void* d_out, int out_size) {
    // num_graphs may or may not be materialized as an input tensor.
    int o = (n_in >= 12) ? 1 : 0;
    const int* x     = (const int*)d_in[0];
    const int* ei    = (const int*)d_in[1];
    const int* et    = (const int*)d_in[2];
    const int* batch = (const int*)d_in[3];
    const int* nt    = (const int*)d_in[4];
    const float* emb    = (const float*)d_in[5 + o];
    const float* w_root = (const float*)d_in[6 + o];
    const float* w_rel  = (const float*)d_in[7 + o];
    const float* bias   = (const float*)d_in[8 + o];
    const float* lw     = (const float*)d_in[9 + o];
    const float* lb     = (const float*)d_in[10 + o];
    float* out = (float*)d_out;

    k_zero<<<(N_NODES * NRELS + 255) / 256, 256>>>();
    k_proj<<<dim3(9, 25), 128>>>(emb, w_rel, w_root);
    k_cnt<<<(N_EDGES + 255) / 256, 256>>>(ei, et);
    k_init<<<(N_NODES * 32 + 255) / 256, 256>>>(x, bias);
    k_edge<<<(N_EDGES * 32) / 256, 256>>>(ei, et, x);
    k_seg<<<(N_NODES + 127) / 128, 128>>>(batch, nt);
    k_out<<<NG, 128>>>(lw, lb, out);
    (void)in_sizes; (void)out_size;
}

// round 3
// speedup vs baseline: 2.4105x; 2.4105x over previous
#include <cuda_runtime.h>

#define N_NODES 100000
#define N_EDGES 1600000
#define NRELS 8
#define HID 128
#define N_TYPES 250
#define NG 64
#define NCLS 49
#define PROJ_COLS 1152   // 8*128 rel columns + 128 root columns
#define MAXDEG 64

// ---- scratch (device globals; no allocation allowed) ----
__device__ __align__(16) float g_proj[N_TYPES * PROJ_COLS];     // 1.15 MB, L2-resident
__device__ int g_cntrel[N_NODES * NRELS];                       // 3.2 MB
__device__ int g_cur[N_NODES];                                  // 400 KB
__device__ unsigned short g_csr[(size_t)N_NODES * MAXDEG];      // 12.8 MB
__device__ float g_seg[NG * HID];
__device__ float g_segcnt[NG];

// Zero the per-replay accumulators.
__global__ void k_zero() {
    int i = blockIdx.x * blockDim.x + threadIdx.x;
    if (i < N_NODES * NRELS) g_cntrel[i] = 0;
    if (i < N_NODES) g_cur[i] = 0;
    if (i < NG * HID) g_seg[i] = 0.f;
    if (i < NG) g_segcnt[i] = 0.f;
}

// proj[t][c] = sum_d emb[t][d] * Wcat[d][c]
//   c in [0,1024): r = c>>7, h = c&127  -> w_rel[r][d][h]
//   c in [1024,1152): h = c-1024        -> w_root[d][h]
__global__ void k_proj(const float* __restrict__ emb,
                       const float* __restrict__ w_rel,
                       const float* __restrict__ w_root) {
    __shared__ float semb[10][128];
    int bx = blockIdx.x;
    int y0 = blockIdx.y * 10;
    int tid = threadIdx.x;
    for (int idx = tid; idx < 10 * 128; idx += 128) {
        int row = idx >> 7, d = idx & 127;
        semb[row][d] = emb[(y0 + row) * 128 + d];
    }
    __syncthreads();
    float acc[10];
#pragma unroll
    for (int t = 0; t < 10; t++) acc[t] = 0.f;
    const float* wp = (bx < 8) ? (w_rel + (size_t)bx * 128 * 128 + tid)
                               : (w_root + tid);
#pragma unroll 4
    for (int d = 0; d < 128; d++) {
        float wv = wp[(size_t)d * 128];
#pragma unroll
        for (int t = 0; t < 10; t++) acc[t] += semb[t][d] * wv;
    }
    int c = bx * 128 + tid;
#pragma unroll
    for (int t = 0; t < 10; t++) g_proj[(y0 + t) * PROJ_COLS + c] = acc[t];
}

// One pass over edges: per-(dst,rel) count + bucket-CSR of 2-byte keys (t*8+r).
// Edges into masked-out (ntype!=0) destinations contribute nothing downstream -> skip.
__global__ void k_build(const int* __restrict__ ei,
                        const int* __restrict__ et,
                        const int* __restrict__ x,
                        const int* __restrict__ nt) {
    int e = blockIdx.x * blockDim.x + threadIdx.x;
    if (e >= N_EDGES) return;
    int dst = ei[N_EDGES + e];
    if (nt[dst] != 0) return;
    int r = et[e];
    int src = ei[e];
    int t = x[src];
    atomicAdd(&g_cntrel[dst * NRELS + r], 1);
    int slot = atomicAdd(&g_cur[dst], 1);
    if (slot < MAXDEG) g_csr[(size_t)dst * MAXDEG + slot] = (unsigned short)(t * NRELS + r);
}

// One warp per (unmasked) node: register accumulation of the 128-float vector.
//   acc = proj[x[n]][root] + bias + sum_i proj[t_i][r_i]/max(cnt[n,r_i],1)
// then ReLU and red.v4 into the 32KB segment table. No g_agg, no float scatter to nodes.
__global__ void k_gather(const int* __restrict__ x,
                         const int* __restrict__ nt,
                         const int* __restrict__ batch,
                         const float* __restrict__ bias) {
    int gt = blockIdx.x * blockDim.x + threadIdx.x;
    int n = gt >> 5;
    int lane = gt & 31;
    if (n >= N_NODES) return;
    if (nt[n] != 0) return;

    const float4* p4 = (const float4*)g_proj;
    int t0 = x[n];
    float4 acc = p4[t0 * (PROJ_COLS / 4) + 256 + lane];
    float4 b = ((const float4*)bias)[lane];
    acc.x += b.x; acc.y += b.y; acc.z += b.z; acc.w += b.w;

    // per-lane rel weight (lanes 0..7), broadcast later via shfl
    int myc = (lane < NRELS) ? g_cntrel[n * NRELS + lane] : 0;
    float myw = 1.0f / fmaxf((float)myc, 1.0f);

    int deg = min(g_cur[n], MAXDEG);
    // lane-parallel key load, broadcast per-iteration via shfl
    const unsigned short* row = g_csr + (size_t)n * MAXDEG;
    int key_a = row[lane];
    int key_b = row[32 + lane];

    for (int i = 0; i < deg; i++) {
        int key = __shfl_sync(0xffffffffu, (i < 32) ? key_a : key_b, i & 31);
        int r = key & (NRELS - 1);
        int t = key >> 3;
        float wr = __shfl_sync(0xffffffffu, myw, r);
        float4 v = p4[t * (PROJ_COLS / 4) + r * 32 + lane];
        acc.x += v.x * wr; acc.y += v.y * wr; acc.z += v.z * wr; acc.w += v.w * wr;
    }

    acc.x = fmaxf(acc.x, 0.f); acc.y = fmaxf(acc.y, 0.f);
    acc.z = fmaxf(acc.z, 0.f); acc.w = fmaxf(acc.w, 0.f);

    int g = batch[n];
    float* dstp = &g_seg[g * HID + lane * 4];
    asm volatile("red.global.add.v4.f32 [%0], {%1,%2,%3,%4};"
                 :: "l"(dstp), "f"(acc.x), "f"(acc.y), "f"(acc.z), "f"(acc.w)
                 : "memory");
    if (lane == 0) atomicAdd(&g_segcnt[g], 1.0f);
}

// out[g][o] = (seg[g]/max(cnt,1)) . lin_w[o] + lin_b[o]
__global__ void k_out(const float* __restrict__ lw,
                      const float* __restrict__ lb,
                      float* __restrict__ out) {
    __shared__ float s[128];
    int g = blockIdx.x, tid = threadIdx.x;
    float c = g_segcnt[g];
    float inv = 1.0f / fmaxf(c, 1.0f);
    s[tid] = g_seg[g * HID + tid] * inv;
    __syncthreads();
    if (tid < NCLS) {
        float acc = lb[tid];
#pragma unroll 4
        for (int d = 0; d < 128; d++) acc += s[d] * lw[tid * 128 + d];
        out[g * NCLS + tid] = acc;
    }
}

extern "C" void kernel_launch(void* const* d_in, const int* in_sizes, int n_in,
                              void* d_out, int out_size) {
    int o = (n_in >= 12) ? 1 : 0;
    const int* x     = (const int*)d_in[0];
    const int* ei    = (const int*)d_in[1];
    const int* et    = (const int*)d_in[2];
    const int* batch = (const int*)d_in[3];
    const int* nt    = (const int*)d_in[4];
    const float* emb    = (const float*)d_in[5 + o];
    const float* w_root = (const float*)d_in[6 + o];
    const float* w_rel  = (const float*)d_in[7 + o];
    const float* bias   = (const float*)d_in[8 + o];
    const float* lw     = (const float*)d_in[9 + o];
    const float* lb     = (const float*)d_in[10 + o];
    float* out = (float*)d_out;

    k_zero<<<(N_NODES * NRELS + 255) / 256, 256>>>();
    k_proj<<<dim3(9, 25), 128>>>(emb, w_rel, w_root);
    k_build<<<(N_EDGES + 255) / 256, 256>>>(ei, et, x, nt);
    k_gather<<<(N_NODES * 32 + 255) / 256, 256>>>(x, nt, batch, bias);
    k_out<<<NG, 128>>>(lw, lb, out);
    (void)in_sizes; (void)out_size;
}